// round 11
// baseline (speedup 1.0000x reference)
#include <cuda_runtime.h>
#include <cuda_fp16.h>
#include <cstdint>

#define NTN 32768
#define CC  128
#define BB  64
#define NN  512
#define HH  4
#define DHD 32
#define EE  524288

// ---------------- scratch ----------------
__device__ float  g_agg[NTN * CC];
__device__ float  g_cnt[NTN];
__device__ __half g_xh[NTN * CC];
__device__ __half g_hl[NTN * CC];
__device__ __half g_qkv[NTN * 384];
__device__ __half g_ao[NTN * CC];
__device__ __half g_ha[NTN * CC];
__device__ __half g_cmb[NTN * CC];
__device__ __half g_hid[NTN * 256];
__device__ __half g_fin[NTN * CC];
__device__ __half g_wh[147456];   // fp16 weights: Wc@0 ipw@16384 opw@65536 Wm1@81920 Wm2@114688
__device__ float  g_stats[768];
__device__ float  g_bnp[6 * CC];
__device__ float  g_ipb[384];

// ---------------- helpers ----------------
__device__ __forceinline__ uint32_t pack_h2(float a, float b) {
    __half2 h = __floats2half2_rn(a, b);
    return *(uint32_t*)&h;
}
__device__ __forceinline__ uint32_t smem_u32(const void* p) {
    return (uint32_t)__cvta_generic_to_shared(p);
}
__device__ __forceinline__ void cpa16(uint32_t dst, const void* src) {
    asm volatile("cp.async.cg.shared.global [%0], [%1], 16;" :: "r"(dst), "l"(src));
}
__device__ __forceinline__ void cpa_commit_wait() {
    asm volatile("cp.async.commit_group;");
    asm volatile("cp.async.wait_group 0;");
}
__device__ __forceinline__ void ldm4(uint32_t* r, uint32_t addr) {
    asm volatile("ldmatrix.sync.aligned.m8n8.x4.shared.b16 {%0,%1,%2,%3}, [%4];"
                 : "=r"(r[0]), "=r"(r[1]), "=r"(r[2]), "=r"(r[3]) : "r"(addr));
}
__device__ __forceinline__ void ldm4t(uint32_t* r, uint32_t addr) {
    asm volatile("ldmatrix.sync.aligned.m8n8.x4.trans.shared.b16 {%0,%1,%2,%3}, [%4];"
                 : "=r"(r[0]), "=r"(r[1]), "=r"(r[2]), "=r"(r[3]) : "r"(addr));
}
__device__ __forceinline__ void mma16(float* c, const uint32_t* a, const uint32_t* b) {
    asm volatile(
        "mma.sync.aligned.m16n8k16.row.col.f32.f16.f16.f32 "
        "{%0,%1,%2,%3}, {%4,%5,%6,%7}, {%8,%9}, {%0,%1,%2,%3};\n"
        : "+f"(c[0]), "+f"(c[1]), "+f"(c[2]), "+f"(c[3])
        : "r"(a[0]), "r"(a[1]), "r"(a[2]), "r"(a[3]), "r"(b[0]), "r"(b[1]));
}
__device__ __forceinline__ void red4(float* addr, float4 v) {
    asm volatile("red.global.add.v4.f32 [%0], {%1,%2,%3,%4};"
                 :: "l"(addr), "f"(v.x), "f"(v.y), "f"(v.z), "f"(v.w) : "memory");
}

// ---------------- setup: zero agg/cnt/stats + x -> fp16 + ipb copy ----------
__global__ void setup_kernel(const float* __restrict__ x, const float* __restrict__ ipb) {
    int i = blockIdx.x * 256 + threadIdx.x;  // float4 index, grid=4096
    ((float4*)g_agg)[i] = make_float4(0.f, 0.f, 0.f, 0.f);
    float4 v = ((const float4*)x)[i];
    uint2 u;
    u.x = pack_h2(v.x, v.y);
    u.y = pack_h2(v.z, v.w);
    ((uint2*)g_xh)[i] = u;
    if (i < NTN) g_cnt[i] = 0.f;
    if (i < 768) g_stats[i] = 0.f;
    if (i < 384) g_ipb[i] = ipb[i];
}

// ---------------- weights -> fp16 ----------------
__global__ void wconv_kernel(const float* __restrict__ Wc, const float* __restrict__ ipw,
                             const float* __restrict__ opw, const float* __restrict__ Wm1,
                             const float* __restrict__ Wm2) {
    int i = blockIdx.x * 256 + threadIdx.x;  // float4 index, grid=144
    const float* src;
    int base;
    if (i < 4096)       { src = Wc;  base = 0; }
    else if (i < 16384) { src = ipw; base = 4096; }
    else if (i < 20480) { src = opw; base = 16384; }
    else if (i < 28672) { src = Wm1; base = 20480; }
    else                { src = Wm2; base = 28672; }
    float4 v = ((const float4*)src)[i - base];
    uint2 u;
    u.x = pack_h2(v.x, v.y);
    u.y = pack_h2(v.z, v.w);
    ((uint2*)g_wh)[i] = u;
}

// ---------------- edge body: warp handles 32 strided edges ----------------
__device__ __forceinline__ void edge_body(int blk, const int* __restrict__ ei) {
    const int lane = threadIdx.x & 31;
    int w = blk * 8 + (threadIdx.x >> 5);  // 16384 warps total
#pragma unroll 4
    for (int e = w; e < EE; e += 16384) {
        int src = __ldg(ei + e);
        int dst = __ldg(ei + EE + e);
        uint2 u = __ldg((const uint2*)(g_xh + (size_t)src * CC + lane * 4));
        float2 f0 = __half22float2(*(__half2*)&u.x);
        float2 f1 = __half22float2(*(__half2*)&u.y);
        red4(g_agg + (size_t)dst * CC + lane * 4, make_float4(f0.x, f0.y, f1.x, f1.y));
        if (lane == 0) atomicAdd(&g_cnt[dst], 1.f);
    }
}

// ---------------- GEMM body: cp.async, W-tile loop, fused epilogues ---------
template <int K, int NT, bool RELU, bool INVCNT, bool COMBINE, bool RESID, bool STATS, typename TIN>
__device__ __forceinline__ void gemm_body(
    int bm, const TIN* __restrict__ X, const __half* __restrict__ X2,
    const __half* __restrict__ Wh, const float* __restrict__ bias,
    const __half* __restrict__ resid, const float* __restrict__ cnt,
    const float* __restrict__ bnp, __half* __restrict__ Y,
    __half* __restrict__ Acopy, float* __restrict__ stats, int Ncols)
{
    constexpr int LD = K + 8;
    constexpr int K8 = K / 8;
    extern __shared__ __half hsm[];
    __half* As = hsm;                     // 128 x LD
    __half* Ws = hsm + 128 * LD;          // 128 x LD
    float* sred = (float*)(hsm + 256 * LD);

    const int t = threadIdx.x, warp = t >> 5, lane = t & 31;
    const int g = lane >> 2, q = lane & 3;
    const int wm = (warp >> 1) * 32, wn = (warp & 1) * 64;
    const unsigned FULL = 0xffffffffu;

    if (STATS) sred[t] = 0.f;

    // ---- stage A (once) ----
    if constexpr (INVCNT) {  // fp32 agg input, scale by 1/max(cnt,1) (K==128)
#pragma unroll
        for (int i = 0; i < 16; i++) {
            int lin = t + i * 256;
            int r = lin >> 5, c4 = (lin & 31) << 2;
            float4 v = *(const float4*)((const float*)X + (size_t)(bm + r) * K + c4);
            float s = 1.f / fmaxf(__ldg(cnt + bm + r), 1.f);
            uint2 u;
            u.x = pack_h2(v.x * s, v.y * s);
            u.y = pack_h2(v.z * s, v.w * s);
            *(uint2*)&As[r * LD + c4] = u;
        }
    } else if constexpr (COMBINE) {  // A = bn1(hl) + bn2(ha), also write Acopy (K==128)
#pragma unroll
        for (int i = 0; i < 8; i++) {
            int lin = t + i * 256;
            int r = lin >> 4, c8 = (lin & 15) << 3;
            uint4 ua = *(const uint4*)((const __half*)X + (size_t)(bm + r) * 128 + c8);
            uint4 ub = *(const uint4*)(X2 + (size_t)(bm + r) * 128 + c8);
            __half2* ah = (__half2*)&ua;
            __half2* bh = (__half2*)&ub;
            uint4 o;
            __half2* oh = (__half2*)&o;
#pragma unroll
            for (int j = 0; j < 4; j++) {
                int cc = c8 + j * 2;
                float2 af = __half22float2(ah[j]);
                float2 bf = __half22float2(bh[j]);
                float o0 = af.x * __ldg(bnp + cc) + __ldg(bnp + 128 + cc)
                         + bf.x * __ldg(bnp + 256 + cc) + __ldg(bnp + 384 + cc);
                float o1 = af.y * __ldg(bnp + cc + 1) + __ldg(bnp + 128 + cc + 1)
                         + bf.y * __ldg(bnp + 256 + cc + 1) + __ldg(bnp + 384 + cc + 1);
                oh[j] = __floats2half2_rn(o0, o1);
            }
            *(uint4*)&As[r * LD + c8] = o;
            *(uint4*)(Acopy + (size_t)(bm + r) * 128 + c8) = o;
        }
    } else {  // fp16 input: cp.async
#pragma unroll
        for (int i = 0; i < 128 * K8 / 256; i++) {
            int lin = t + i * 256;
            int r = lin / K8, c8 = (lin % K8) * 8;
            cpa16(smem_u32(&As[r * LD + c8]), (const __half*)X + (size_t)(bm + r) * K + c8);
        }
    }

    const int lr = lane & 7, lm = lane >> 3;
    uint32_t a_addr[2], w_addr[4];
#pragma unroll
    for (int mi = 0; mi < 2; mi++)
        a_addr[mi] = smem_u32(&As[(wm + mi * 16 + (lm & 1) * 8 + lr) * LD + (lm >> 1) * 8]);
#pragma unroll
    for (int p = 0; p < 4; p++)
        w_addr[p] = smem_u32(&Ws[(wn + p * 16 + (lm >> 1) * 8 + lr) * LD + (lm & 1) * 8]);

#pragma unroll 1
    for (int nt = 0; nt < NT; nt++) {
        if (nt > 0) __syncthreads();  // all warps done reading Ws
#pragma unroll
        for (int i = 0; i < 128 * K8 / 256; i++) {
            int lin = t + i * 256;
            int r = lin / K8, c8 = (lin % K8) * 8;
            cpa16(smem_u32(&Ws[r * LD + c8]), Wh + (size_t)(nt * 128 + r) * K + c8);
        }
        cpa_commit_wait();  // waits W (and A on nt==0)
        __syncthreads();

        float acc[2][8][4];
#pragma unroll
        for (int mi = 0; mi < 2; mi++)
#pragma unroll
            for (int ni = 0; ni < 8; ni++)
#pragma unroll
                for (int j = 0; j < 4; j++) acc[mi][ni][j] = 0.f;

#pragma unroll
        for (int ks = 0; ks < K / 16; ks++) {
            uint32_t a[2][4];
            ldm4(a[0], a_addr[0] + ks * 32);
            ldm4(a[1], a_addr[1] + ks * 32);
#pragma unroll
            for (int p = 0; p < 4; p++) {
                uint32_t b[4];
                ldm4(b, w_addr[p] + ks * 32);
#pragma unroll
                for (int mi = 0; mi < 2; mi++) {
                    mma16(acc[mi][p * 2 + 0], a[mi], &b[0]);
                    mma16(acc[mi][p * 2 + 1], a[mi], &b[2]);
                }
            }
        }

        // epilogue
        float s0[16], s1[16];
        if constexpr (STATS) {
#pragma unroll
            for (int i = 0; i < 16; i++) { s0[i] = 0.f; s1[i] = 0.f; }
        }
        const int bncol = nt * 128;
#pragma unroll
        for (int mi = 0; mi < 2; mi++) {
            int r0 = bm + wm + mi * 16 + g;
#pragma unroll
            for (int ni = 0; ni < 8; ni++) {
                int c0 = bncol + wn + ni * 8 + 2 * q;
                float b0 = __ldg(bias + c0), b1 = __ldg(bias + c0 + 1);
#pragma unroll
                for (int h2 = 0; h2 < 2; h2++) {
                    int r = r0 + h2 * 8;
                    float v0 = acc[mi][ni][h2 * 2 + 0] + b0;
                    float v1 = acc[mi][ni][h2 * 2 + 1] + b1;
                    if (RELU) { v0 = fmaxf(v0, 0.f); v1 = fmaxf(v1, 0.f); }
                    if (RESID) {
                        uint32_t ru = *(const uint32_t*)(resid + (size_t)r * Ncols + c0);
                        float2 rf = __half22float2(*(__half2*)&ru);
                        v0 += rf.x;
                        v1 += rf.y;
                    }
                    if constexpr (STATS) {
                        s0[ni * 2 + 0] += v0; s1[ni * 2 + 0] += v0 * v0;
                        s0[ni * 2 + 1] += v1; s1[ni * 2 + 1] += v1 * v1;
                    }
                    *(uint32_t*)(Y + (size_t)r * Ncols + c0) = pack_h2(v0, v1);
                }
            }
        }
        if constexpr (STATS) {
#pragma unroll
            for (int i = 0; i < 16; i++) {
#pragma unroll
                for (int d = 4; d < 32; d <<= 1) {
                    s0[i] += __shfl_xor_sync(FULL, s0[i], d);
                    s1[i] += __shfl_xor_sync(FULL, s1[i], d);
                }
            }
            if (g == 0) {
#pragma unroll
                for (int ni = 0; ni < 8; ni++) {
                    int c = wn + ni * 8 + 2 * q;
                    atomicAdd(&sred[c], s0[ni * 2]);
                    atomicAdd(&sred[c + 1], s0[ni * 2 + 1]);
                    atomicAdd(&sred[128 + c], s1[ni * 2]);
                    atomicAdd(&sred[128 + c + 1], s1[ni * 2 + 1]);
                }
            }
            __syncthreads();
            atomicAdd(&stats[t], sred[t]);
        }
    }
}

// ---------------- fp16 flash attention (device body) ----------------
__device__ __forceinline__ void attn_body(int blk, const __half* __restrict__ qkv,
                                          __half* __restrict__ ao)
{
    extern __shared__ __half asm_[];
    __half* Qs = asm_;                   // 128 x 40
    __half* Ks = asm_ + 128 * 40;        // 2 x 64 x 40
    __half* Vs = asm_ + 128 * 40 + 2 * 64 * 40;
    const int BUFH = 64 * 40;

    const int b = blk >> 4;
    const int h = (blk >> 2) & 3;
    const int qt = blk & 3;
    const int t = threadIdx.x;
    const int lane = t & 31, warp = t >> 5, g = lane >> 2, q = lane & 3;
    const int wr = warp * 16;
    const unsigned FULL = 0xffffffffu;
    const __half2 qs2 = __floats2half2_rn(0.17677669529663687f, 0.17677669529663687f);

    const __half* qbase = qkv + (size_t)(b * NN + qt * 128) * 384 + h * 32;
#pragma unroll
    for (int i = 0; i < 2; i++) {
        int lin = t + i * 256;
        int r = lin >> 2, c8 = (lin & 3) * 8;
        uint4 u = *(const uint4*)(qbase + (size_t)r * 384 + c8);
        __half2* hp = (__half2*)&u;
#pragma unroll
        for (int j = 0; j < 4; j++) hp[j] = __hmul2(hp[j], qs2);
        *(uint4*)&Qs[r * 40 + c8] = u;
    }

    const int skr = t >> 2, skc = (t & 3) * 8;
    const __half* kvbase = qkv + (size_t)(b * NN) * 384 + h * 32 + 128;
    {
        const __half* p = kvbase + (size_t)skr * 384 + skc;
        *(uint4*)&Ks[skr * 40 + skc] = *(const uint4*)p;
        *(uint4*)&Vs[skr * 40 + skc] = *(const uint4*)(p + 128);
    }
    __syncthreads();

    const int lr = lane & 7, lm = lane >> 3;
    uint32_t aq[2][4];
    {
        uint32_t qaddr = smem_u32(&Qs[(wr + (lm & 1) * 8 + lr) * 40 + (lm >> 1) * 8]);
        ldm4(aq[0], qaddr);
        ldm4(aq[1], qaddr + 32);
    }
    uint32_t kaddr[4];
#pragma unroll
    for (int p = 0; p < 4; p++)
        kaddr[p] = smem_u32(&Ks[(p * 16 + (lm >> 1) * 8 + lr) * 40 + (lm & 1) * 8]);
    uint32_t vaddr = smem_u32(&Vs[((lm & 1) * 8 + lr) * 40 + (lm >> 1) * 8]);

    float m0 = -1e30f, m1 = -1e30f, l0 = 0.f, l1 = 0.f;
    float oacc[4][4];
#pragma unroll
    for (int ni = 0; ni < 4; ni++)
#pragma unroll
        for (int j = 0; j < 4; j++) oacc[ni][j] = 0.f;

#pragma unroll 1
    for (int kt = 0; kt < 8; kt++) {
        const int cur = kt & 1;
        const uint32_t boff = cur * (BUFH * 2);
        uint4 pk, pv;
        if (kt < 7) {
            const __half* p = kvbase + (size_t)(kt + 1) * 64 * 384 + (size_t)skr * 384 + skc;
            pk = *(const uint4*)p;
            pv = *(const uint4*)(p + 128);
        }

        float sacc[8][4];
#pragma unroll
        for (int ni = 0; ni < 8; ni++)
#pragma unroll
            for (int j = 0; j < 4; j++) sacc[ni][j] = 0.f;
#pragma unroll
        for (int ks = 0; ks < 2; ks++) {
#pragma unroll
            for (int p = 0; p < 4; p++) {
                uint32_t bk[4];
                ldm4(bk, kaddr[p] + boff + ks * 32);
                mma16(sacc[p * 2 + 0], aq[ks], &bk[0]);
                mma16(sacc[p * 2 + 1], aq[ks], &bk[2]);
            }
        }

        float cm0 = -1e30f, cm1 = -1e30f;
#pragma unroll
        for (int ni = 0; ni < 8; ni++) {
            cm0 = fmaxf(cm0, fmaxf(sacc[ni][0], sacc[ni][1]));
            cm1 = fmaxf(cm1, fmaxf(sacc[ni][2], sacc[ni][3]));
        }
        cm0 = fmaxf(cm0, __shfl_xor_sync(FULL, cm0, 1));
        cm0 = fmaxf(cm0, __shfl_xor_sync(FULL, cm0, 2));
        cm1 = fmaxf(cm1, __shfl_xor_sync(FULL, cm1, 1));
        cm1 = fmaxf(cm1, __shfl_xor_sync(FULL, cm1, 2));
        float nm0 = fmaxf(m0, cm0), nm1 = fmaxf(m1, cm1);
        float al0 = __expf(m0 - nm0), al1 = __expf(m1 - nm1);
        float sum0 = 0.f, sum1 = 0.f;
#pragma unroll
        for (int ni = 0; ni < 8; ni++) {
            sacc[ni][0] = __expf(sacc[ni][0] - nm0);
            sacc[ni][1] = __expf(sacc[ni][1] - nm0);
            sacc[ni][2] = __expf(sacc[ni][2] - nm1);
            sacc[ni][3] = __expf(sacc[ni][3] - nm1);
            sum0 += sacc[ni][0] + sacc[ni][1];
            sum1 += sacc[ni][2] + sacc[ni][3];
        }
        sum0 += __shfl_xor_sync(FULL, sum0, 1);
        sum0 += __shfl_xor_sync(FULL, sum0, 2);
        sum1 += __shfl_xor_sync(FULL, sum1, 1);
        sum1 += __shfl_xor_sync(FULL, sum1, 2);
        l0 = l0 * al0 + sum0;
        l1 = l1 * al1 + sum1;
        m0 = nm0;
        m1 = nm1;
#pragma unroll
        for (int ni = 0; ni < 4; ni++) {
            oacc[ni][0] *= al0;
            oacc[ni][1] *= al0;
            oacc[ni][2] *= al1;
            oacc[ni][3] *= al1;
        }

        uint32_t ap[4][4];
#pragma unroll
        for (int ks = 0; ks < 4; ks++) {
            ap[ks][0] = pack_h2(sacc[2 * ks][0], sacc[2 * ks][1]);
            ap[ks][1] = pack_h2(sacc[2 * ks][2], sacc[2 * ks][3]);
            ap[ks][2] = pack_h2(sacc[2 * ks + 1][0], sacc[2 * ks + 1][1]);
            ap[ks][3] = pack_h2(sacc[2 * ks + 1][2], sacc[2 * ks + 1][3]);
        }

#pragma unroll
        for (int ks = 0; ks < 4; ks++) {
            uint32_t bv0[4], bv1[4];
            ldm4t(bv0, vaddr + boff + ks * 1280);
            ldm4t(bv1, vaddr + boff + ks * 1280 + 32);
            mma16(oacc[0], ap[ks], &bv0[0]);
            mma16(oacc[1], ap[ks], &bv0[2]);
            mma16(oacc[2], ap[ks], &bv1[0]);
            mma16(oacc[3], ap[ks], &bv1[2]);
        }

        if (kt < 7) {
            *(uint4*)&Ks[(cur ^ 1) * BUFH + skr * 40 + skc] = pk;
            *(uint4*)&Vs[(cur ^ 1) * BUFH + skr * 40 + skc] = pv;
        }
        __syncthreads();
    }

    float il0 = 1.f / l0, il1 = 1.f / l1;
    int q0 = b * NN + qt * 128 + wr + g;
#pragma unroll
    for (int ni = 0; ni < 4; ni++) {
        int c = h * 32 + ni * 8 + 2 * q;
        *(uint32_t*)(ao + (size_t)q0 * CC + c) = pack_h2(oacc[ni][0] * il0, oacc[ni][1] * il0);
        *(uint32_t*)(ao + (size_t)(q0 + 8) * CC + c) = pack_h2(oacc[ni][2] * il1, oacc[ni][3] * il1);
    }
}

// ---------------- fused launches ----------------
#define EDGE_BLKS 2048

// F1: edge aggregation (blocks [0,2048)) + qkv GEMM (blocks [2048,2304))
__global__ __launch_bounds__(256) void f1_kernel(const int* __restrict__ ei) {
    if (blockIdx.x < EDGE_BLKS) {
        edge_body(blockIdx.x, ei);
    } else {
        gemm_body<128, 3, false, false, false, false, false, __half>(
            (blockIdx.x - EDGE_BLKS) * 128, g_xh, nullptr, g_wh + 16384,
            g_ipb, nullptr, nullptr, nullptr, g_qkv, nullptr, nullptr, 384);
    }
}

// F2: attention (blocks [0,1024)) + local GEMM (blocks [1024,1280))
__global__ __launch_bounds__(256) void f2_kernel(const float* __restrict__ bc) {
    if (blockIdx.x < 1024) {
        attn_body(blockIdx.x, g_qkv, g_ao);
    } else {
        gemm_body<128, 1, false, true, false, true, true, float>(
            (blockIdx.x - 1024) * 128, g_agg, nullptr, g_wh, bc,
            g_xh, g_cnt, nullptr, g_hl, nullptr, g_stats, 128);
    }
}

// standalone GEMM wrappers
template <int K, int NT, bool RELU, bool INVCNT, bool COMBINE, bool RESID, bool STATS, typename TIN>
__global__ __launch_bounds__(256) void gemm3(
    const TIN* __restrict__ X, const __half* __restrict__ X2,
    const __half* __restrict__ Wh, const float* __restrict__ bias,
    const __half* __restrict__ resid, const float* __restrict__ bnp,
    __half* __restrict__ Y, __half* __restrict__ Acopy,
    float* __restrict__ stats, int Ncols)
{
    gemm_body<K, NT, RELU, INVCNT, COMBINE, RESID, STATS, TIN>(
        blockIdx.x * 128, X, X2, Wh, bias, resid, nullptr, bnp, Y, Acopy, stats, Ncols);
}

// ---------------- BN finalize / final apply ----------------
__global__ void finalize2_kernel(const float* __restrict__ gn1, const float* __restrict__ bn1,
                                 const float* __restrict__ gn2, const float* __restrict__ bn2) {
    int c = threadIdx.x;
    int s = blockIdx.x;
    const float* gamma = s ? gn2 : gn1;
    const float* beta = s ? bn2 : bn1;
    float mean = g_stats[s * 256 + c] * (1.f / NTN);
    float var = g_stats[s * 256 + CC + c] * (1.f / NTN) - mean * mean;
    float sc = gamma[c] * rsqrtf(var + 1e-5f);
    g_bnp[s * 256 + c] = sc;
    g_bnp[s * 256 + CC + c] = beta[c] - mean * sc;
}

__global__ void finalize_kernel(const float* __restrict__ stats,
                                const float* __restrict__ gamma,
                                const float* __restrict__ beta,
                                float* __restrict__ bnp) {
    int c = threadIdx.x;
    float mean = stats[c] * (1.f / NTN);
    float var = stats[CC + c] * (1.f / NTN) - mean * mean;
    float sc = gamma[c] * rsqrtf(var + 1e-5f);
    bnp[c] = sc;
    bnp[CC + c] = beta[c] - mean * sc;
}

__global__ void apply_bn_kernel(const float* __restrict__ bnp, float* __restrict__ dst) {
    int i = blockIdx.x * 256 + threadIdx.x;  // uint4 index (8 halfs), grid=2048
    int c = (i & 15) * 8;
    uint4 v = ((const uint4*)g_fin)[i];
    __half2* vh = (__half2*)&v;
    float r[8];
#pragma unroll
    for (int j = 0; j < 4; j++) {
        int cc = c + j * 2;
        float2 vf = __half22float2(vh[j]);
        r[j * 2 + 0] = vf.x * __ldg(bnp + cc) + __ldg(bnp + 128 + cc);
        r[j * 2 + 1] = vf.y * __ldg(bnp + cc + 1) + __ldg(bnp + 128 + cc + 1);
    }
    ((float4*)dst)[i * 2 + 0] = make_float4(r[0], r[1], r[2], r[3]);
    ((float4*)dst)[i * 2 + 1] = make_float4(r[4], r[5], r[6], r[7]);
}

// ---------------- launch ----------------
extern "C" void kernel_launch(void* const* d_in, const int* in_sizes, int n_in,
                              void* d_out, int out_size) {
    const float* x = (const float*)d_in[0];
    const int* ei = (const int*)d_in[1];
    const float* Wc = (const float*)d_in[2];
    const float* bc = (const float*)d_in[3];
    const float* ipw = (const float*)d_in[4];
    const float* ipb = (const float*)d_in[5];
    const float* opw = (const float*)d_in[6];
    const float* opb = (const float*)d_in[7];
    const float* gn1 = (const float*)d_in[8];
    const float* bn1 = (const float*)d_in[9];
    const float* gn2 = (const float*)d_in[10];
    const float* bn2 = (const float*)d_in[11];
    const float* gn3 = (const float*)d_in[12];
    const float* bn3 = (const float*)d_in[13];
    const float* Wm1 = (const float*)d_in[14];
    const float* bm1 = (const float*)d_in[15];
    const float* Wm2 = (const float*)d_in[16];
    const float* bm2 = (const float*)d_in[17];
    float* out = (float*)d_out;

    float *p_stats, *p_bnp;
    __half *p_hl, *p_ao, *p_ha, *p_cmb, *p_hid, *p_fin, *p_wh, *p_xh;
    cudaGetSymbolAddress((void**)&p_hl, g_hl);
    cudaGetSymbolAddress((void**)&p_ao, g_ao);
    cudaGetSymbolAddress((void**)&p_ha, g_ha);
    cudaGetSymbolAddress((void**)&p_cmb, g_cmb);
    cudaGetSymbolAddress((void**)&p_hid, g_hid);
    cudaGetSymbolAddress((void**)&p_fin, g_fin);
    cudaGetSymbolAddress((void**)&p_wh, g_wh);
    cudaGetSymbolAddress((void**)&p_xh, g_xh);
    cudaGetSymbolAddress((void**)&p_stats, g_stats);
    cudaGetSymbolAddress((void**)&p_bnp, g_bnp);

    const int smK128 = 2 * 256 * 136 + 1024;   // 70,656 B
    const int smK256 = 2 * 256 * 264 + 1024;   // 136,192 B

    auto kOut   = gemm3<128, 1, false, false, false, true,  true,  __half>;
    auto kMlp1  = gemm3<128, 2, true,  false, true,  false, false, __half>;
    auto kMlp2  = gemm3<256, 1, false, false, false, true,  true,  __half>;
    cudaFuncSetAttribute((const void*)f1_kernel, cudaFuncAttributeMaxDynamicSharedMemorySize, smK128);
    cudaFuncSetAttribute((const void*)f2_kernel, cudaFuncAttributeMaxDynamicSharedMemorySize, smK128);
    cudaFuncSetAttribute((const void*)kOut,   cudaFuncAttributeMaxDynamicSharedMemorySize, smK128);
    cudaFuncSetAttribute((const void*)kMlp1,  cudaFuncAttributeMaxDynamicSharedMemorySize, smK128);
    cudaFuncSetAttribute((const void*)kMlp2,  cudaFuncAttributeMaxDynamicSharedMemorySize, smK256);

    setup_kernel<<<4096, 256>>>(x, ipb);
    wconv_kernel<<<144, 256>>>(Wc, ipw, opw, Wm1, Wm2);

    // F1: edge aggregation || qkv projection
    f1_kernel<<<EDGE_BLKS + 256, 256, smK128>>>(ei);

    // F2: attention || local GEMM (+fused BN1 stats)
    f2_kernel<<<1024 + 256, 256, smK128>>>(bc);

    // out_proj (+fused BN2 stats)
    kOut<<<256, 256, smK128>>>(p_ao, nullptr, p_wh + 65536, opb, p_xh, nullptr,
                               p_ha, nullptr, p_stats + 256, 128);

    // BN1 + BN2 params (one launch)
    finalize2_kernel<<<2, 128>>>(gn1, bn1, gn2, bn2);

    // MLP (combine fused into A staging; cmb written out for residual)
    kMlp1<<<256, 256, smK128>>>(p_hl, p_ha, p_wh + 81920, bm1, nullptr, p_bnp,
                                p_hid, p_cmb, nullptr, 256);
    kMlp2<<<256, 256, smK256>>>(p_hid, nullptr, p_wh + 114688, bm2, p_cmb, nullptr,
                                p_fin, nullptr, p_stats + 512, 128);

    // BN3 -> output
    finalize_kernel<<<1, 128>>>(p_stats + 512, gn3, bn3, p_bnp + 512);
    apply_bn_kernel<<<2048, 256>>>(p_bnp + 512, out);
}

// round 16
// speedup vs baseline: 1.2011x; 1.2011x over previous
#include <cuda_runtime.h>
#include <cuda_fp16.h>
#include <cstdint>

#define NTN 32768
#define CC  128
#define BB  64
#define NN  512
#define HH  4
#define DHD 32
#define EE  524288

// ---------------- scratch ----------------
__device__ float  g_agg[NTN * CC];
__device__ float  g_cnt[NTN];
__device__ __half g_xh[NTN * CC];
__device__ __half g_hl[NTN * CC];
__device__ __half g_qkv[NTN * 384];
__device__ __half g_ao[NTN * CC];
__device__ __half g_ha[NTN * CC];
__device__ __half g_cmb[NTN * CC];
__device__ __half g_hid[NTN * 256];
__device__ __half g_fin[NTN * CC];
__device__ __half g_wh[147456];   // fp16 weights: Wc@0 ipw@16384 opw@65536 Wm1@81920 Wm2@114688
__device__ float  g_stats[768];
__device__ float  g_bnp[6 * CC];

// ---------------- helpers ----------------
__device__ __forceinline__ uint32_t pack_h2(float a, float b) {
    __half2 h = __floats2half2_rn(a, b);
    return *(uint32_t*)&h;
}
__device__ __forceinline__ uint32_t smem_u32(const void* p) {
    return (uint32_t)__cvta_generic_to_shared(p);
}
__device__ __forceinline__ void cpa16(uint32_t dst, const void* src) {
    asm volatile("cp.async.cg.shared.global [%0], [%1], 16;" :: "r"(dst), "l"(src));
}
__device__ __forceinline__ void cpa_commit_wait() {
    asm volatile("cp.async.commit_group;");
    asm volatile("cp.async.wait_group 0;");
}
__device__ __forceinline__ void ldm4(uint32_t* r, uint32_t addr) {
    asm volatile("ldmatrix.sync.aligned.m8n8.x4.shared.b16 {%0,%1,%2,%3}, [%4];"
                 : "=r"(r[0]), "=r"(r[1]), "=r"(r[2]), "=r"(r[3]) : "r"(addr));
}
__device__ __forceinline__ void ldm4t(uint32_t* r, uint32_t addr) {
    asm volatile("ldmatrix.sync.aligned.m8n8.x4.trans.shared.b16 {%0,%1,%2,%3}, [%4];"
                 : "=r"(r[0]), "=r"(r[1]), "=r"(r[2]), "=r"(r[3]) : "r"(addr));
}
__device__ __forceinline__ void mma16(float* c, const uint32_t* a, const uint32_t* b) {
    asm volatile(
        "mma.sync.aligned.m16n8k16.row.col.f32.f16.f16.f32 "
        "{%0,%1,%2,%3}, {%4,%5,%6,%7}, {%8,%9}, {%0,%1,%2,%3};\n"
        : "+f"(c[0]), "+f"(c[1]), "+f"(c[2]), "+f"(c[3])
        : "r"(a[0]), "r"(a[1]), "r"(a[2]), "r"(a[3]), "r"(b[0]), "r"(b[1]));
}
__device__ __forceinline__ void red4(float* addr, float4 v) {
    asm volatile("red.global.add.v4.f32 [%0], {%1,%2,%3,%4};"
                 :: "l"(addr), "f"(v.x), "f"(v.y), "f"(v.z), "f"(v.w) : "memory");
}

// ---------------- setup: zero agg/cnt/stats + x -> fp16 ----------------
__global__ void setup_kernel(const float* __restrict__ x) {
    int i = blockIdx.x * 256 + threadIdx.x;  // float4 index, grid=4096
    ((float4*)g_agg)[i] = make_float4(0.f, 0.f, 0.f, 0.f);
    float4 v = ((const float4*)x)[i];
    uint2 u;
    u.x = pack_h2(v.x, v.y);
    u.y = pack_h2(v.z, v.w);
    ((uint2*)g_xh)[i] = u;
    if (i < NTN) g_cnt[i] = 0.f;
    if (i < 768) g_stats[i] = 0.f;
}

// ---------------- weights -> fp16 ----------------
__global__ void wconv_kernel(const float* __restrict__ Wc, const float* __restrict__ ipw,
                             const float* __restrict__ opw, const float* __restrict__ Wm1,
                             const float* __restrict__ Wm2) {
    int i = blockIdx.x * 256 + threadIdx.x;  // float4 index, grid=144
    const float* src;
    int base;
    if (i < 4096)       { src = Wc;  base = 0; }
    else if (i < 16384) { src = ipw; base = 4096; }
    else if (i < 20480) { src = opw; base = 16384; }
    else if (i < 28672) { src = Wm1; base = 20480; }
    else                { src = Wm2; base = 28672; }
    float4 v = ((const float4*)src)[i - base];
    uint2 u;
    u.x = pack_h2(v.x, v.y);
    u.y = pack_h2(v.z, v.w);
    ((uint2*)g_wh)[i] = u;
}

// ---------------- edge aggregation: warp per edge (measured variant) --------
__global__ void edge_kernel(const int* __restrict__ ei) {
    int gw = (blockIdx.x * blockDim.x + threadIdx.x) >> 5;
    int lane = threadIdx.x & 31;
    int src = ei[gw];
    int dst = ei[EE + gw];
    uint2 u = __ldg((const uint2*)(g_xh + (size_t)src * CC + lane * 4));
    float2 f0 = __half22float2(*(__half2*)&u.x);
    float2 f1 = __half22float2(*(__half2*)&u.y);
    red4(g_agg + (size_t)dst * CC + lane * 4, make_float4(f0.x, f0.y, f1.x, f1.y));
    if (lane == 0) atomicAdd(&g_cnt[dst], 1.f);
}

// ---------------- GEMM: cp.async, W-tile loop, fused epilogues --------------
// Y[:, nt*128..] = act(A[128 rows, K] @ Wh[nt*128..+128, K]^T + bias) (+resid)
template <int K, int NT, bool RELU, bool INVCNT, bool COMBINE, bool RESID, bool STATS, typename TIN>
__global__ __launch_bounds__(256) void gemm3(
    const TIN* __restrict__ X, const __half* __restrict__ X2,
    const __half* __restrict__ Wh, const float* __restrict__ bias,
    const __half* __restrict__ resid, const float* __restrict__ cnt,
    const float* __restrict__ bnp, __half* __restrict__ Y,
    __half* __restrict__ Acopy, float* __restrict__ stats, int Ncols)
{
    constexpr int LD = K + 8;
    constexpr int K8 = K / 8;
    extern __shared__ __half hsm[];
    __half* As = hsm;                     // 128 x LD
    __half* Ws = hsm + 128 * LD;          // 128 x LD
    float* sred = (float*)(hsm + 256 * LD);

    const int bm = blockIdx.x * 128;
    const int t = threadIdx.x, warp = t >> 5, lane = t & 31;
    const int g = lane >> 2, q = lane & 3;
    const int wm = (warp >> 1) * 32, wn = (warp & 1) * 64;
    const unsigned FULL = 0xffffffffu;

    if (STATS) sred[t] = 0.f;

    // ---- stage A (once) ----
    if constexpr (INVCNT) {  // fp32 agg input, scale by 1/max(cnt,1) (K==128)
#pragma unroll
        for (int i = 0; i < 16; i++) {
            int lin = t + i * 256;
            int r = lin >> 5, c4 = (lin & 31) << 2;
            float4 v = *(const float4*)((const float*)X + (size_t)(bm + r) * K + c4);
            float s = 1.f / fmaxf(__ldg(cnt + bm + r), 1.f);
            uint2 u;
            u.x = pack_h2(v.x * s, v.y * s);
            u.y = pack_h2(v.z * s, v.w * s);
            *(uint2*)&As[r * LD + c4] = u;
        }
    } else if constexpr (COMBINE) {  // A = bn1(hl) + bn2(ha), also write Acopy (K==128)
#pragma unroll
        for (int i = 0; i < 8; i++) {
            int lin = t + i * 256;
            int r = lin >> 4, c8 = (lin & 15) << 3;
            uint4 ua = *(const uint4*)((const __half*)X + (size_t)(bm + r) * 128 + c8);
            uint4 ub = *(const uint4*)(X2 + (size_t)(bm + r) * 128 + c8);
            __half2* ah = (__half2*)&ua;
            __half2* bh = (__half2*)&ub;
            uint4 o;
            __half2* oh = (__half2*)&o;
#pragma unroll
            for (int j = 0; j < 4; j++) {
                int cc = c8 + j * 2;
                float2 af = __half22float2(ah[j]);
                float2 bf = __half22float2(bh[j]);
                float o0 = af.x * __ldg(bnp + cc) + __ldg(bnp + 128 + cc)
                         + bf.x * __ldg(bnp + 256 + cc) + __ldg(bnp + 384 + cc);
                float o1 = af.y * __ldg(bnp + cc + 1) + __ldg(bnp + 128 + cc + 1)
                         + bf.y * __ldg(bnp + 256 + cc + 1) + __ldg(bnp + 384 + cc + 1);
                oh[j] = __floats2half2_rn(o0, o1);
            }
            *(uint4*)&As[r * LD + c8] = o;
            *(uint4*)(Acopy + (size_t)(bm + r) * 128 + c8) = o;
        }
    } else {  // fp16 input: cp.async
#pragma unroll
        for (int i = 0; i < 128 * K8 / 256; i++) {
            int lin = t + i * 256;
            int r = lin / K8, c8 = (lin % K8) * 8;
            cpa16(smem_u32(&As[r * LD + c8]), (const __half*)X + (size_t)(bm + r) * K + c8);
        }
    }

    const int lr = lane & 7, lm = lane >> 3;
    uint32_t a_addr[2], w_addr[4];
#pragma unroll
    for (int mi = 0; mi < 2; mi++)
        a_addr[mi] = smem_u32(&As[(wm + mi * 16 + (lm & 1) * 8 + lr) * LD + (lm >> 1) * 8]);
#pragma unroll
    for (int p = 0; p < 4; p++)
        w_addr[p] = smem_u32(&Ws[(wn + p * 16 + (lm >> 1) * 8 + lr) * LD + (lm & 1) * 8]);

#pragma unroll 1
    for (int nt = 0; nt < NT; nt++) {
        if (nt > 0) __syncthreads();  // all warps done reading Ws
#pragma unroll
        for (int i = 0; i < 128 * K8 / 256; i++) {
            int lin = t + i * 256;
            int r = lin / K8, c8 = (lin % K8) * 8;
            cpa16(smem_u32(&Ws[r * LD + c8]), Wh + (size_t)(nt * 128 + r) * K + c8);
        }
        cpa_commit_wait();  // waits W (and A on nt==0)
        __syncthreads();

        float acc[2][8][4];
#pragma unroll
        for (int mi = 0; mi < 2; mi++)
#pragma unroll
            for (int ni = 0; ni < 8; ni++)
#pragma unroll
                for (int j = 0; j < 4; j++) acc[mi][ni][j] = 0.f;

#pragma unroll
        for (int ks = 0; ks < K / 16; ks++) {
            uint32_t a[2][4];
            ldm4(a[0], a_addr[0] + ks * 32);
            ldm4(a[1], a_addr[1] + ks * 32);
#pragma unroll
            for (int p = 0; p < 4; p++) {
                uint32_t b[4];
                ldm4(b, w_addr[p] + ks * 32);
#pragma unroll
                for (int mi = 0; mi < 2; mi++) {
                    mma16(acc[mi][p * 2 + 0], a[mi], &b[0]);
                    mma16(acc[mi][p * 2 + 1], a[mi], &b[2]);
                }
            }
        }

        // epilogue
        float s0[16], s1[16];
        if constexpr (STATS) {
#pragma unroll
            for (int i = 0; i < 16; i++) { s0[i] = 0.f; s1[i] = 0.f; }
        }
        const int bncol = nt * 128;
#pragma unroll
        for (int mi = 0; mi < 2; mi++) {
            int r0 = bm + wm + mi * 16 + g;
#pragma unroll
            for (int ni = 0; ni < 8; ni++) {
                int c0 = bncol + wn + ni * 8 + 2 * q;
                float b0 = __ldg(bias + c0), b1 = __ldg(bias + c0 + 1);
#pragma unroll
                for (int h2 = 0; h2 < 2; h2++) {
                    int r = r0 + h2 * 8;
                    float v0 = acc[mi][ni][h2 * 2 + 0] + b0;
                    float v1 = acc[mi][ni][h2 * 2 + 1] + b1;
                    if (RELU) { v0 = fmaxf(v0, 0.f); v1 = fmaxf(v1, 0.f); }
                    if (RESID) {
                        uint32_t ru = *(const uint32_t*)(resid + (size_t)r * Ncols + c0);
                        float2 rf = __half22float2(*(__half2*)&ru);
                        v0 += rf.x;
                        v1 += rf.y;
                    }
                    if constexpr (STATS) {
                        s0[ni * 2 + 0] += v0; s1[ni * 2 + 0] += v0 * v0;
                        s0[ni * 2 + 1] += v1; s1[ni * 2 + 1] += v1 * v1;
                    }
                    *(uint32_t*)(Y + (size_t)r * Ncols + c0) = pack_h2(v0, v1);
                }
            }
        }
        if constexpr (STATS) {
#pragma unroll
            for (int i = 0; i < 16; i++) {
#pragma unroll
                for (int d = 4; d < 32; d <<= 1) {
                    s0[i] += __shfl_xor_sync(FULL, s0[i], d);
                    s1[i] += __shfl_xor_sync(FULL, s1[i], d);
                }
            }
            if (g == 0) {
#pragma unroll
                for (int ni = 0; ni < 8; ni++) {
                    int c = wn + ni * 8 + 2 * q;
                    atomicAdd(&sred[c], s0[ni * 2]);
                    atomicAdd(&sred[c + 1], s0[ni * 2 + 1]);
                    atomicAdd(&sred[128 + c], s1[ni * 2]);
                    atomicAdd(&sred[128 + c + 1], s1[ni * 2 + 1]);
                }
            }
            __syncthreads();
            atomicAdd(&stats[t], sred[t]);
        }
    }
}

// ---------------- fp16 flash attention (standalone, 30.7 KB smem) -----------
__global__ __launch_bounds__(256) void attn_kernel(const __half* __restrict__ qkv,
                                                   __half* __restrict__ ao)
{
    extern __shared__ __half asm_[];
    __half* Qs = asm_;                   // 128 x 40
    __half* Ks = asm_ + 128 * 40;        // 2 x 64 x 40
    __half* Vs = asm_ + 128 * 40 + 2 * 64 * 40;
    const int BUFH = 64 * 40;

    const int blk = blockIdx.x;
    const int b = blk >> 4;
    const int h = (blk >> 2) & 3;
    const int qt = blk & 3;
    const int t = threadIdx.x;
    const int lane = t & 31, warp = t >> 5, g = lane >> 2, q = lane & 3;
    const int wr = warp * 16;
    const unsigned FULL = 0xffffffffu;
    const __half2 qs2 = __floats2half2_rn(0.17677669529663687f, 0.17677669529663687f);

    const __half* qbase = qkv + (size_t)(b * NN + qt * 128) * 384 + h * 32;
#pragma unroll
    for (int i = 0; i < 2; i++) {
        int lin = t + i * 256;
        int r = lin >> 2, c8 = (lin & 3) * 8;
        uint4 u = *(const uint4*)(qbase + (size_t)r * 384 + c8);
        __half2* hp = (__half2*)&u;
#pragma unroll
        for (int j = 0; j < 4; j++) hp[j] = __hmul2(hp[j], qs2);
        *(uint4*)&Qs[r * 40 + c8] = u;
    }

    const int skr = t >> 2, skc = (t & 3) * 8;
    const __half* kvbase = qkv + (size_t)(b * NN) * 384 + h * 32 + 128;
    {
        const __half* p = kvbase + (size_t)skr * 384 + skc;
        *(uint4*)&Ks[skr * 40 + skc] = *(const uint4*)p;
        *(uint4*)&Vs[skr * 40 + skc] = *(const uint4*)(p + 128);
    }
    __syncthreads();

    const int lr = lane & 7, lm = lane >> 3;
    uint32_t aq[2][4];
    {
        uint32_t qaddr = smem_u32(&Qs[(wr + (lm & 1) * 8 + lr) * 40 + (lm >> 1) * 8]);
        ldm4(aq[0], qaddr);
        ldm4(aq[1], qaddr + 32);
    }
    uint32_t kaddr[4];
#pragma unroll
    for (int p = 0; p < 4; p++)
        kaddr[p] = smem_u32(&Ks[(p * 16 + (lm >> 1) * 8 + lr) * 40 + (lm & 1) * 8]);
    uint32_t vaddr = smem_u32(&Vs[((lm & 1) * 8 + lr) * 40 + (lm >> 1) * 8]);

    float m0 = -1e30f, m1 = -1e30f, l0 = 0.f, l1 = 0.f;
    float oacc[4][4];
#pragma unroll
    for (int ni = 0; ni < 4; ni++)
#pragma unroll
        for (int j = 0; j < 4; j++) oacc[ni][j] = 0.f;

#pragma unroll 1
    for (int kt = 0; kt < 8; kt++) {
        const int cur = kt & 1;
        const uint32_t boff = cur * (BUFH * 2);
        uint4 pk, pv;
        if (kt < 7) {
            const __half* p = kvbase + (size_t)(kt + 1) * 64 * 384 + (size_t)skr * 384 + skc;
            pk = *(const uint4*)p;
            pv = *(const uint4*)(p + 128);
        }

        float sacc[8][4];
#pragma unroll
        for (int ni = 0; ni < 8; ni++)
#pragma unroll
            for (int j = 0; j < 4; j++) sacc[ni][j] = 0.f;
#pragma unroll
        for (int ks = 0; ks < 2; ks++) {
#pragma unroll
            for (int p = 0; p < 4; p++) {
                uint32_t bk[4];
                ldm4(bk, kaddr[p] + boff + ks * 32);
                mma16(sacc[p * 2 + 0], aq[ks], &bk[0]);
                mma16(sacc[p * 2 + 1], aq[ks], &bk[2]);
            }
        }

        float cm0 = -1e30f, cm1 = -1e30f;
#pragma unroll
        for (int ni = 0; ni < 8; ni++) {
            cm0 = fmaxf(cm0, fmaxf(sacc[ni][0], sacc[ni][1]));
            cm1 = fmaxf(cm1, fmaxf(sacc[ni][2], sacc[ni][3]));
        }
        cm0 = fmaxf(cm0, __shfl_xor_sync(FULL, cm0, 1));
        cm0 = fmaxf(cm0, __shfl_xor_sync(FULL, cm0, 2));
        cm1 = fmaxf(cm1, __shfl_xor_sync(FULL, cm1, 1));
        cm1 = fmaxf(cm1, __shfl_xor_sync(FULL, cm1, 2));
        float nm0 = fmaxf(m0, cm0), nm1 = fmaxf(m1, cm1);
        float al0 = __expf(m0 - nm0), al1 = __expf(m1 - nm1);
        float sum0 = 0.f, sum1 = 0.f;
#pragma unroll
        for (int ni = 0; ni < 8; ni++) {
            sacc[ni][0] = __expf(sacc[ni][0] - nm0);
            sacc[ni][1] = __expf(sacc[ni][1] - nm0);
            sacc[ni][2] = __expf(sacc[ni][2] - nm1);
            sacc[ni][3] = __expf(sacc[ni][3] - nm1);
            sum0 += sacc[ni][0] + sacc[ni][1];
            sum1 += sacc[ni][2] + sacc[ni][3];
        }
        sum0 += __shfl_xor_sync(FULL, sum0, 1);
        sum0 += __shfl_xor_sync(FULL, sum0, 2);
        sum1 += __shfl_xor_sync(FULL, sum1, 1);
        sum1 += __shfl_xor_sync(FULL, sum1, 2);
        l0 = l0 * al0 + sum0;
        l1 = l1 * al1 + sum1;
        m0 = nm0;
        m1 = nm1;
#pragma unroll
        for (int ni = 0; ni < 4; ni++) {
            oacc[ni][0] *= al0;
            oacc[ni][1] *= al0;
            oacc[ni][2] *= al1;
            oacc[ni][3] *= al1;
        }

        uint32_t ap[4][4];
#pragma unroll
        for (int ks = 0; ks < 4; ks++) {
            ap[ks][0] = pack_h2(sacc[2 * ks][0], sacc[2 * ks][1]);
            ap[ks][1] = pack_h2(sacc[2 * ks][2], sacc[2 * ks][3]);
            ap[ks][2] = pack_h2(sacc[2 * ks + 1][0], sacc[2 * ks + 1][1]);
            ap[ks][3] = pack_h2(sacc[2 * ks + 1][2], sacc[2 * ks + 1][3]);
        }

#pragma unroll
        for (int ks = 0; ks < 4; ks++) {
            uint32_t bv0[4], bv1[4];
            ldm4t(bv0, vaddr + boff + ks * 1280);
            ldm4t(bv1, vaddr + boff + ks * 1280 + 32);
            mma16(oacc[0], ap[ks], &bv0[0]);
            mma16(oacc[1], ap[ks], &bv0[2]);
            mma16(oacc[2], ap[ks], &bv1[0]);
            mma16(oacc[3], ap[ks], &bv1[2]);
        }

        if (kt < 7) {
            *(uint4*)&Ks[(cur ^ 1) * BUFH + skr * 40 + skc] = pk;
            *(uint4*)&Vs[(cur ^ 1) * BUFH + skr * 40 + skc] = pv;
        }
        __syncthreads();
    }

    float il0 = 1.f / l0, il1 = 1.f / l1;
    int q0 = b * NN + qt * 128 + wr + g;
#pragma unroll
    for (int ni = 0; ni < 4; ni++) {
        int c = h * 32 + ni * 8 + 2 * q;
        *(uint32_t*)(ao + (size_t)q0 * CC + c) = pack_h2(oacc[ni][0] * il0, oacc[ni][1] * il0);
        *(uint32_t*)(ao + (size_t)(q0 + 8) * CC + c) = pack_h2(oacc[ni][2] * il1, oacc[ni][3] * il1);
    }
}

// ---------------- BN finalize / final apply ----------------
__global__ void finalize2_kernel(const float* __restrict__ gn1, const float* __restrict__ bn1,
                                 const float* __restrict__ gn2, const float* __restrict__ bn2) {
    int c = threadIdx.x;
    int s = blockIdx.x;
    const float* gamma = s ? gn2 : gn1;
    const float* beta = s ? bn2 : bn1;
    float mean = g_stats[s * 256 + c] * (1.f / NTN);
    float var = g_stats[s * 256 + CC + c] * (1.f / NTN) - mean * mean;
    float sc = gamma[c] * rsqrtf(var + 1e-5f);
    g_bnp[s * 256 + c] = sc;
    g_bnp[s * 256 + CC + c] = beta[c] - mean * sc;
}

__global__ void finalize_kernel(const float* __restrict__ stats,
                                const float* __restrict__ gamma,
                                const float* __restrict__ beta,
                                float* __restrict__ bnp) {
    int c = threadIdx.x;
    float mean = stats[c] * (1.f / NTN);
    float var = stats[CC + c] * (1.f / NTN) - mean * mean;
    float sc = gamma[c] * rsqrtf(var + 1e-5f);
    bnp[c] = sc;
    bnp[CC + c] = beta[c] - mean * sc;
}

__global__ void apply_bn_kernel(const float* __restrict__ bnp, float* __restrict__ dst) {
    int i = blockIdx.x * 256 + threadIdx.x;  // uint4 index (8 halfs), grid=2048
    int c = (i & 15) * 8;
    uint4 v = ((const uint4*)g_fin)[i];
    __half2* vh = (__half2*)&v;
    float r[8];
#pragma unroll
    for (int j = 0; j < 4; j++) {
        int cc = c + j * 2;
        float2 vf = __half22float2(vh[j]);
        r[j * 2 + 0] = vf.x * __ldg(bnp + cc) + __ldg(bnp + 128 + cc);
        r[j * 2 + 1] = vf.y * __ldg(bnp + cc + 1) + __ldg(bnp + 128 + cc + 1);
    }
    ((float4*)dst)[i * 2 + 0] = make_float4(r[0], r[1], r[2], r[3]);
    ((float4*)dst)[i * 2 + 1] = make_float4(r[4], r[5], r[6], r[7]);
}

// ---------------- launch ----------------
extern "C" void kernel_launch(void* const* d_in, const int* in_sizes, int n_in,
                              void* d_out, int out_size) {
    const float* x = (const float*)d_in[0];
    const int* ei = (const int*)d_in[1];
    const float* Wc = (const float*)d_in[2];
    const float* bc = (const float*)d_in[3];
    const float* ipw = (const float*)d_in[4];
    const float* ipb = (const float*)d_in[5];
    const float* opw = (const float*)d_in[6];
    const float* opb = (const float*)d_in[7];
    const float* gn1 = (const float*)d_in[8];
    const float* bn1 = (const float*)d_in[9];
    const float* gn2 = (const float*)d_in[10];
    const float* bn2 = (const float*)d_in[11];
    const float* gn3 = (const float*)d_in[12];
    const float* bn3 = (const float*)d_in[13];
    const float* Wm1 = (const float*)d_in[14];
    const float* bm1 = (const float*)d_in[15];
    const float* Wm2 = (const float*)d_in[16];
    const float* bm2 = (const float*)d_in[17];
    float* out = (float*)d_out;

    float *p_agg, *p_cnt, *p_stats, *p_bnp;
    __half *p_xh, *p_hl, *p_qkv, *p_ao, *p_ha, *p_cmb, *p_hid, *p_fin, *p_wh;
    cudaGetSymbolAddress((void**)&p_agg, g_agg);
    cudaGetSymbolAddress((void**)&p_cnt, g_cnt);
    cudaGetSymbolAddress((void**)&p_xh, g_xh);
    cudaGetSymbolAddress((void**)&p_hl, g_hl);
    cudaGetSymbolAddress((void**)&p_qkv, g_qkv);
    cudaGetSymbolAddress((void**)&p_ao, g_ao);
    cudaGetSymbolAddress((void**)&p_ha, g_ha);
    cudaGetSymbolAddress((void**)&p_cmb, g_cmb);
    cudaGetSymbolAddress((void**)&p_hid, g_hid);
    cudaGetSymbolAddress((void**)&p_fin, g_fin);
    cudaGetSymbolAddress((void**)&p_wh, g_wh);
    cudaGetSymbolAddress((void**)&p_stats, g_stats);
    cudaGetSymbolAddress((void**)&p_bnp, g_bnp);

    const int smK128 = 2 * 256 * 136 + 1024;   // 70,656 B
    const int smK256 = 2 * 256 * 264 + 1024;   // 136,192 B
    const int smattn = (128 * 40 + 4 * 64 * 40) * 2;  // 30,720 B

    auto kLocal = gemm3<128, 1, false, true,  false, true,  true,  float>;
    auto kQkv   = gemm3<128, 3, false, false, false, false, false, __half>;
    auto kOut   = gemm3<128, 1, false, false, false, true,  true,  __half>;
    auto kMlp1  = gemm3<128, 2, true,  false, true,  false, false, __half>;
    auto kMlp2  = gemm3<256, 1, false, false, false, true,  true,  __half>;
    cudaFuncSetAttribute((const void*)kLocal, cudaFuncAttributeMaxDynamicSharedMemorySize, smK128);
    cudaFuncSetAttribute((const void*)kQkv,   cudaFuncAttributeMaxDynamicSharedMemorySize, smK128);
    cudaFuncSetAttribute((const void*)kOut,   cudaFuncAttributeMaxDynamicSharedMemorySize, smK128);
    cudaFuncSetAttribute((const void*)kMlp1,  cudaFuncAttributeMaxDynamicSharedMemorySize, smK128);
    cudaFuncSetAttribute((const void*)kMlp2,  cudaFuncAttributeMaxDynamicSharedMemorySize, smK256);
    cudaFuncSetAttribute((const void*)attn_kernel, cudaFuncAttributeMaxDynamicSharedMemorySize, smattn);

    setup_kernel<<<4096, 256>>>(x);
    wconv_kernel<<<144, 256>>>(Wc, ipw, opw, Wm1, Wm2);
    edge_kernel<<<65536, 256>>>(ei);

    // local branch (invcnt + stats fused -> stats[0:256])
    kLocal<<<256, 256, smK128>>>(p_agg, nullptr, p_wh, bc, p_xh, p_cnt, nullptr,
                                 p_hl, nullptr, p_stats, 128);

    // global branch
    kQkv<<<256, 256, smK128>>>(p_xh, nullptr, p_wh + 16384, ipb, nullptr, nullptr, nullptr,
                               p_qkv, nullptr, nullptr, 384);
    attn_kernel<<<1024, 256, smattn>>>(p_qkv, p_ao);
    kOut<<<256, 256, smK128>>>(p_ao, nullptr, p_wh + 65536, opb, p_xh, nullptr, nullptr,
                               p_ha, nullptr, p_stats + 256, 128);

    // BN1 + BN2 params (one launch)
    finalize2_kernel<<<2, 128>>>(gn1, bn1, gn2, bn2);

    // MLP (combine fused into A staging; cmb written out for residual)
    kMlp1<<<256, 256, smK128>>>(p_hl, p_ha, p_wh + 81920, bm1, nullptr, nullptr, p_bnp,
                                p_hid, p_cmb, nullptr, 256);
    kMlp2<<<256, 256, smK256>>>(p_hid, nullptr, p_wh + 114688, bm2, p_cmb, nullptr, nullptr,
                                p_fin, nullptr, p_stats + 512, 128);

    // BN3 -> output
    finalize_kernel<<<1, 128>>>(p_stats + 512, gn3, bn3, p_bnp + 512);
    apply_bn_kernel<<<2048, 256>>>(p_bnp + 512, out);
}